// round 9
// baseline (speedup 1.0000x reference)
#include <cuda_runtime.h>

// MK-MMD, linear-time estimator, fully fused single kernel:
//   loss = (1/B) * sum_i sum_alpha [ K(|zs_i-zs_j|^2) + K(|zt_i-zt_j|^2)
//                                  - K(|zs_i-zt_j|^2) - K(|zs_j-zt_i|^2) ], j=(i+1)%B
//   K(d) = exp(-d / (2*alpha*mean_d2))
//   mean_d2 = (2*N*sum(f^2) - 2*||colsum(f)||^2)/N^2, f=[zs;zt], N=2B
// Each block handles NI=8 consecutive i's with a sliding row window (rows
// 8k..8k+8 of zs and zt), owns rows 8k..8k+7 for colsum/sumsq (exact cover),
// and the last block to finish (atomic ticket) does the scalar finalize.
// State self-resets at the end of each call -> graph-replay safe.

static const int BN = 2048;          // B
static const int D4 = 256;           // D/4 floats4 per row
static const int NI = 8;             // i's per block
static const int NBLK = BN / NI;     // 256 blocks

__device__ float4   g_colsum4[D4];   // zero-init at load; self-reset each call
__device__ float    g_sumsq;
__device__ unsigned g_count;
__device__ float4   g_dist4[BN];     // {ss, tt, st, ts} per i

__device__ __forceinline__ float dot4(float4 a) {
    return a.x * a.x + a.y * a.y + a.z * a.z + a.w * a.w;
}
__device__ __forceinline__ float sq4(float4 a, float4 b) {
    float x = a.x - b.x, y = a.y - b.y, z = a.z - b.z, w = a.w - b.w;
    return x * x + y * y + z * z + w * w;
}
__device__ __forceinline__ float wred(float v) {
    #pragma unroll
    for (int o = 16; o > 0; o >>= 1) v += __shfl_down_sync(0xffffffffu, v, o);
    return v;
}

__global__ __launch_bounds__(256)
void mmd_fused(const float4* __restrict__ zs, const float4* __restrict__ zt,
               float* __restrict__ out) {
    const int t = threadIdx.x, w = t >> 5, lane = t & 31;
    const int base = blockIdx.x * NI;

    __shared__ float s_d[8][NI][4];   // [warp][i-offset][comp], conflict-free gather
    __shared__ float s_ss[8];
    __shared__ float s_red[8];
    __shared__ float s_coef[3];
    __shared__ int   s_flag;

    // sliding window: (a, c) = current rows zs_i, zt_i
    float4 a = zs[(base << 8) + t];
    float4 c = zt[(base << 8) + t];
    float4 col = make_float4(a.x + c.x, a.y + c.y, a.z + c.z, a.w + c.w);
    float  ss  = dot4(a) + dot4(c);

    #pragma unroll
    for (int r = 0; r < NI; r++) {
        const int jrow = (base + r + 1) & (BN - 1);
        float4 b = zs[(jrow << 8) + t];
        float4 e = zt[(jrow << 8) + t];
        float v0 = wred(sq4(a, b));   // |zs_i - zs_j|^2
        float v1 = wred(sq4(c, e));   // |zt_i - zt_j|^2
        float v2 = wred(sq4(a, e));   // |zs_i - zt_j|^2
        float v3 = wred(sq4(b, c));   // |zs_j - zt_i|^2
        if (lane == 0) {
            s_d[w][r][0] = v0; s_d[w][r][1] = v1;
            s_d[w][r][2] = v2; s_d[w][r][3] = v3;
        }
        if (r < NI - 1) {   // rows base+1 .. base+7 owned (base done at init)
            col.x += b.x + e.x; col.y += b.y + e.y;
            col.z += b.z + e.z; col.w += b.w + e.w;
            ss += dot4(b) + dot4(e);
        }
        a = b; c = e;
    }
    ss = wred(ss);
    if (lane == 0) s_ss[w] = ss;
    __syncthreads();

    // colsum contribution: 4 float atomics per thread (spread addresses)
    float* gc = (float*)g_colsum4;
    atomicAdd(gc + 4 * t + 0, col.x);
    atomicAdd(gc + 4 * t + 1, col.y);
    atomicAdd(gc + 4 * t + 2, col.z);
    atomicAdd(gc + 4 * t + 3, col.w);

    // distance outputs: 32 threads, one (i, comp) each
    if (t < NI * 4) {
        const int r = t >> 2, comp = t & 3;
        float s = 0.f;
        #pragma unroll
        for (int ww = 0; ww < 8; ww++) s += s_d[ww][r][comp];
        ((float*)g_dist4)[(base + r) * 4 + comp] = s;
    }
    if (t == 0) {
        float sb = 0.f;
        #pragma unroll
        for (int ww = 0; ww < 8; ww++) sb += s_ss[ww];
        atomicAdd(&g_sumsq, sb);
    }

    // ---- ticket: last block finalizes (threadfence-reduction pattern) ----
    __threadfence();
    __syncthreads();
    if (t == 0) s_flag = (atomicAdd(&g_count, 1u) == NBLK - 1);
    __syncthreads();
    if (!s_flag) return;

    // ---------------- tail finalize (one block, 256 threads) --------------
    float4 cs = __ldcg(&g_colsum4[t]);
    float sq = wred(dot4(cs));
    if (lane == 0) s_red[w] = sq;
    g_colsum4[t] = make_float4(0.f, 0.f, 0.f, 0.f);   // reset for next call
    __syncthreads();
    if (t == 0) {
        float S2 = 0.f;
        #pragma unroll
        for (int ww = 0; ww < 8; ww++) S2 += s_red[ww];
        double SSd = (double)__ldcg((const float*)&g_sumsq);
        const double N = 2.0 * (double)BN;
        double mean_d2 = (2.0 * N * SSd - 2.0 * (double)S2) / (N * N);
        const double alphas[3] = {0.5, 1.0, 2.0};
        #pragma unroll
        for (int aa = 0; aa < 3; aa++)
            s_coef[aa] = (float)(-1.0 / (2.0 * alphas[aa] * mean_d2));
        g_sumsq = 0.f;     // reset
        g_count = 0u;      // reset
    }
    __syncthreads();

    const float c0 = s_coef[0], c1 = s_coef[1], c2 = s_coef[2];
    float local = 0.f;
    #pragma unroll
    for (int kk = 0; kk < BN / 256; kk++) {
        float4 d = __ldcg(&g_dist4[kk * 256 + t]);
        local += __expf(c0 * d.x) + __expf(c0 * d.y) - __expf(c0 * d.z) - __expf(c0 * d.w);
        local += __expf(c1 * d.x) + __expf(c1 * d.y) - __expf(c1 * d.z) - __expf(c1 * d.w);
        local += __expf(c2 * d.x) + __expf(c2 * d.y) - __expf(c2 * d.z) - __expf(c2 * d.w);
    }
    local = wred(local);
    if (lane == 0) s_red[w] = local;
    __syncthreads();
    if (t == 0) {
        float tot = 0.f;
        #pragma unroll
        for (int ww = 0; ww < 8; ww++) tot += s_red[ww];
        out[0] = tot / (float)BN;
    }
}

extern "C" void kernel_launch(void* const* d_in, const int* in_sizes, int n_in,
                              void* d_out, int out_size) {
    const float4* zs = (const float4*)d_in[0];
    const float4* zt = (const float4*)d_in[1];
    mmd_fused<<<NBLK, 256>>>(zs, zt, (float*)d_out);
}

// round 10
// speedup vs baseline: 1.0015x; 1.0015x over previous
#include <cuda_runtime.h>

// MK-MMD, linear-time estimator, fully fused single kernel:
//   loss = (1/B) * sum_i sum_alpha [ K(|zs_i-zs_j|^2) + K(|zt_i-zt_j|^2)
//                                  - K(|zs_i-zt_j|^2) - K(|zs_j-zt_i|^2) ], j=(i+1)%B
//   K(d) = exp(-d / (2*alpha*mean_d2))
//   mean_d2 = (2*N*sum(f^2) - 2*||colsum(f)||^2)/N^2, f=[zs;zt], N=2B
// Each block handles NI=8 consecutive i's with a sliding row window (rows
// 8k..8k+8 of zs and zt), owns rows 8k..8k+7 for colsum/sumsq (exact cover),
// and the last block to finish (atomic ticket) does the scalar finalize.
// State self-resets at the end of each call -> graph-replay safe.

static const int BN = 2048;          // B
static const int D4 = 256;           // D/4 floats4 per row
static const int NI = 8;             // i's per block
static const int NBLK = BN / NI;     // 256 blocks

__device__ float4   g_colsum4[D4];   // zero-init at load; self-reset each call
__device__ float    g_sumsq;
__device__ unsigned g_count;
__device__ float4   g_dist4[BN];     // {ss, tt, st, ts} per i

__device__ __forceinline__ float dot4(float4 a) {
    return a.x * a.x + a.y * a.y + a.z * a.z + a.w * a.w;
}
__device__ __forceinline__ float sq4(float4 a, float4 b) {
    float x = a.x - b.x, y = a.y - b.y, z = a.z - b.z, w = a.w - b.w;
    return x * x + y * y + z * z + w * w;
}
__device__ __forceinline__ float wred(float v) {
    #pragma unroll
    for (int o = 16; o > 0; o >>= 1) v += __shfl_down_sync(0xffffffffu, v, o);
    return v;
}

__global__ __launch_bounds__(256)
void mmd_fused(const float4* __restrict__ zs, const float4* __restrict__ zt,
               float* __restrict__ out) {
    const int t = threadIdx.x, w = t >> 5, lane = t & 31;
    const int base = blockIdx.x * NI;

    __shared__ float s_d[8][NI][4];   // [warp][i-offset][comp], conflict-free gather
    __shared__ float s_ss[8];
    __shared__ float s_red[8];
    __shared__ float s_coef[3];
    __shared__ int   s_flag;

    // sliding window: (a, c) = current rows zs_i, zt_i
    float4 a = zs[(base << 8) + t];
    float4 c = zt[(base << 8) + t];
    float4 col = make_float4(a.x + c.x, a.y + c.y, a.z + c.z, a.w + c.w);
    float  ss  = dot4(a) + dot4(c);

    #pragma unroll
    for (int r = 0; r < NI; r++) {
        const int jrow = (base + r + 1) & (BN - 1);
        float4 b = zs[(jrow << 8) + t];
        float4 e = zt[(jrow << 8) + t];
        float v0 = wred(sq4(a, b));   // |zs_i - zs_j|^2
        float v1 = wred(sq4(c, e));   // |zt_i - zt_j|^2
        float v2 = wred(sq4(a, e));   // |zs_i - zt_j|^2
        float v3 = wred(sq4(b, c));   // |zs_j - zt_i|^2
        if (lane == 0) {
            s_d[w][r][0] = v0; s_d[w][r][1] = v1;
            s_d[w][r][2] = v2; s_d[w][r][3] = v3;
        }
        if (r < NI - 1) {   // rows base+1 .. base+7 owned (base done at init)
            col.x += b.x + e.x; col.y += b.y + e.y;
            col.z += b.z + e.z; col.w += b.w + e.w;
            ss += dot4(b) + dot4(e);
        }
        a = b; c = e;
    }
    ss = wred(ss);
    if (lane == 0) s_ss[w] = ss;
    __syncthreads();

    // colsum contribution: 4 float atomics per thread (spread addresses)
    float* gc = (float*)g_colsum4;
    atomicAdd(gc + 4 * t + 0, col.x);
    atomicAdd(gc + 4 * t + 1, col.y);
    atomicAdd(gc + 4 * t + 2, col.z);
    atomicAdd(gc + 4 * t + 3, col.w);

    // distance outputs: 32 threads, one (i, comp) each
    if (t < NI * 4) {
        const int r = t >> 2, comp = t & 3;
        float s = 0.f;
        #pragma unroll
        for (int ww = 0; ww < 8; ww++) s += s_d[ww][r][comp];
        ((float*)g_dist4)[(base + r) * 4 + comp] = s;
    }
    if (t == 0) {
        float sb = 0.f;
        #pragma unroll
        for (int ww = 0; ww < 8; ww++) sb += s_ss[ww];
        atomicAdd(&g_sumsq, sb);
    }

    // ---- ticket: last block finalizes (threadfence-reduction pattern) ----
    __threadfence();
    __syncthreads();
    if (t == 0) s_flag = (atomicAdd(&g_count, 1u) == NBLK - 1);
    __syncthreads();
    if (!s_flag) return;

    // ---------------- tail finalize (one block, 256 threads) --------------
    float4 cs = __ldcg(&g_colsum4[t]);
    float sq = wred(dot4(cs));
    if (lane == 0) s_red[w] = sq;
    g_colsum4[t] = make_float4(0.f, 0.f, 0.f, 0.f);   // reset for next call
    __syncthreads();
    if (t == 0) {
        float S2 = 0.f;
        #pragma unroll
        for (int ww = 0; ww < 8; ww++) S2 += s_red[ww];
        double SSd = (double)__ldcg((const float*)&g_sumsq);
        const double N = 2.0 * (double)BN;
        double mean_d2 = (2.0 * N * SSd - 2.0 * (double)S2) / (N * N);
        const double alphas[3] = {0.5, 1.0, 2.0};
        #pragma unroll
        for (int aa = 0; aa < 3; aa++)
            s_coef[aa] = (float)(-1.0 / (2.0 * alphas[aa] * mean_d2));
        g_sumsq = 0.f;     // reset
        g_count = 0u;      // reset
    }
    __syncthreads();

    const float c0 = s_coef[0], c1 = s_coef[1], c2 = s_coef[2];
    float local = 0.f;
    #pragma unroll
    for (int kk = 0; kk < BN / 256; kk++) {
        float4 d = __ldcg(&g_dist4[kk * 256 + t]);
        local += __expf(c0 * d.x) + __expf(c0 * d.y) - __expf(c0 * d.z) - __expf(c0 * d.w);
        local += __expf(c1 * d.x) + __expf(c1 * d.y) - __expf(c1 * d.z) - __expf(c1 * d.w);
        local += __expf(c2 * d.x) + __expf(c2 * d.y) - __expf(c2 * d.z) - __expf(c2 * d.w);
    }
    local = wred(local);
    if (lane == 0) s_red[w] = local;
    __syncthreads();
    if (t == 0) {
        float tot = 0.f;
        #pragma unroll
        for (int ww = 0; ww < 8; ww++) tot += s_red[ww];
        out[0] = tot / (float)BN;
    }
}

extern "C" void kernel_launch(void* const* d_in, const int* in_sizes, int n_in,
                              void* d_out, int out_size) {
    const float4* zs = (const float4*)d_in[0];
    const float4* zt = (const float4*)d_in[1];
    mmd_fused<<<NBLK, 256>>>(zs, zt, (float*)d_out);
}

// round 11
// speedup vs baseline: 1.0137x; 1.0122x over previous
#include <cuda_runtime.h>

// MK-MMD, linear-time estimator, fully fused single kernel:
//   loss = (1/B) * sum_i sum_alpha [ K(|zs_i-zs_j|^2) + K(|zt_i-zt_j|^2)
//                                  - K(|zs_i-zt_j|^2) - K(|zs_j-zt_i|^2) ], j=(i+1)%B
//   K(d) = exp(-d / (2*alpha*mean_d2))
//   mean_d2 = (2*N*sum(f^2) - 2*||colsum(f)||^2)/N^2, f=[zs;zt], N=2B
// Each block handles NI=8 consecutive i's with a sliding row window (rows
// 8k..8k+8 of zs and zt), owns rows 8k..8k+7 for colsum/sumsq (exact cover),
// and the last block to finish (atomic ticket) does the scalar finalize.
// State self-resets at the end of each call -> graph-replay safe.

static const int BN = 2048;          // B
static const int D4 = 256;           // D/4 floats4 per row
static const int NI = 8;             // i's per block
static const int NBLK = BN / NI;     // 256 blocks

__device__ float4   g_colsum4[D4];   // zero-init at load; self-reset each call
__device__ float    g_sumsq;
__device__ unsigned g_count;
__device__ float4   g_dist4[BN];     // {ss, tt, st, ts} per i

__device__ __forceinline__ float dot4(float4 a) {
    return a.x * a.x + a.y * a.y + a.z * a.z + a.w * a.w;
}
__device__ __forceinline__ float sq4(float4 a, float4 b) {
    float x = a.x - b.x, y = a.y - b.y, z = a.z - b.z, w = a.w - b.w;
    return x * x + y * y + z * z + w * w;
}
__device__ __forceinline__ float wred(float v) {
    #pragma unroll
    for (int o = 16; o > 0; o >>= 1) v += __shfl_down_sync(0xffffffffu, v, o);
    return v;
}

__global__ __launch_bounds__(256)
void mmd_fused(const float4* __restrict__ zs, const float4* __restrict__ zt,
               float* __restrict__ out) {
    const int t = threadIdx.x, w = t >> 5, lane = t & 31;
    const int base = blockIdx.x * NI;

    __shared__ float s_d[8][NI][4];   // [warp][i-offset][comp], conflict-free gather
    __shared__ float s_ss[8];
    __shared__ float s_red[8];
    __shared__ float s_coef[3];
    __shared__ int   s_flag;

    // sliding window: (a, c) = current rows zs_i, zt_i
    float4 a = zs[(base << 8) + t];
    float4 c = zt[(base << 8) + t];
    float4 col = make_float4(a.x + c.x, a.y + c.y, a.z + c.z, a.w + c.w);
    float  ss  = dot4(a) + dot4(c);

    #pragma unroll
    for (int r = 0; r < NI; r++) {
        const int jrow = (base + r + 1) & (BN - 1);
        float4 b = zs[(jrow << 8) + t];
        float4 e = zt[(jrow << 8) + t];
        float v0 = wred(sq4(a, b));   // |zs_i - zs_j|^2
        float v1 = wred(sq4(c, e));   // |zt_i - zt_j|^2
        float v2 = wred(sq4(a, e));   // |zs_i - zt_j|^2
        float v3 = wred(sq4(b, c));   // |zs_j - zt_i|^2
        if (lane == 0) {
            s_d[w][r][0] = v0; s_d[w][r][1] = v1;
            s_d[w][r][2] = v2; s_d[w][r][3] = v3;
        }
        if (r < NI - 1) {   // rows base+1 .. base+7 owned (base done at init)
            col.x += b.x + e.x; col.y += b.y + e.y;
            col.z += b.z + e.z; col.w += b.w + e.w;
            ss += dot4(b) + dot4(e);
        }
        a = b; c = e;
    }
    ss = wred(ss);
    if (lane == 0) s_ss[w] = ss;
    __syncthreads();

    // colsum contribution: 4 float atomics per thread (spread addresses)
    float* gc = (float*)g_colsum4;
    atomicAdd(gc + 4 * t + 0, col.x);
    atomicAdd(gc + 4 * t + 1, col.y);
    atomicAdd(gc + 4 * t + 2, col.z);
    atomicAdd(gc + 4 * t + 3, col.w);

    // distance outputs: 32 threads, one (i, comp) each
    if (t < NI * 4) {
        const int r = t >> 2, comp = t & 3;
        float s = 0.f;
        #pragma unroll
        for (int ww = 0; ww < 8; ww++) s += s_d[ww][r][comp];
        ((float*)g_dist4)[(base + r) * 4 + comp] = s;
    }
    if (t == 0) {
        float sb = 0.f;
        #pragma unroll
        for (int ww = 0; ww < 8; ww++) sb += s_ss[ww];
        atomicAdd(&g_sumsq, sb);
    }

    // ---- ticket: last block finalizes (threadfence-reduction pattern) ----
    __threadfence();
    __syncthreads();
    if (t == 0) s_flag = (atomicAdd(&g_count, 1u) == NBLK - 1);
    __syncthreads();
    if (!s_flag) return;

    // ---------------- tail finalize (one block, 256 threads) --------------
    float4 cs = __ldcg(&g_colsum4[t]);
    float sq = wred(dot4(cs));
    if (lane == 0) s_red[w] = sq;
    g_colsum4[t] = make_float4(0.f, 0.f, 0.f, 0.f);   // reset for next call
    __syncthreads();
    if (t == 0) {
        float S2 = 0.f;
        #pragma unroll
        for (int ww = 0; ww < 8; ww++) S2 += s_red[ww];
        double SSd = (double)__ldcg((const float*)&g_sumsq);
        const double N = 2.0 * (double)BN;
        double mean_d2 = (2.0 * N * SSd - 2.0 * (double)S2) / (N * N);
        const double alphas[3] = {0.5, 1.0, 2.0};
        #pragma unroll
        for (int aa = 0; aa < 3; aa++)
            s_coef[aa] = (float)(-1.0 / (2.0 * alphas[aa] * mean_d2));
        g_sumsq = 0.f;     // reset
        g_count = 0u;      // reset
    }
    __syncthreads();

    const float c0 = s_coef[0], c1 = s_coef[1], c2 = s_coef[2];
    float local = 0.f;
    #pragma unroll
    for (int kk = 0; kk < BN / 256; kk++) {
        float4 d = __ldcg(&g_dist4[kk * 256 + t]);
        local += __expf(c0 * d.x) + __expf(c0 * d.y) - __expf(c0 * d.z) - __expf(c0 * d.w);
        local += __expf(c1 * d.x) + __expf(c1 * d.y) - __expf(c1 * d.z) - __expf(c1 * d.w);
        local += __expf(c2 * d.x) + __expf(c2 * d.y) - __expf(c2 * d.z) - __expf(c2 * d.w);
    }
    local = wred(local);
    if (lane == 0) s_red[w] = local;
    __syncthreads();
    if (t == 0) {
        float tot = 0.f;
        #pragma unroll
        for (int ww = 0; ww < 8; ww++) tot += s_red[ww];
        out[0] = tot / (float)BN;
    }
}

extern "C" void kernel_launch(void* const* d_in, const int* in_sizes, int n_in,
                              void* d_out, int out_size) {
    const float4* zs = (const float4*)d_in[0];
    const float4* zt = (const float4*)d_in[1];
    mmd_fused<<<NBLK, 256>>>(zs, zt, (float*)d_out);
}